// round 1
// baseline (speedup 1.0000x reference)
#include <cuda_runtime.h>

// log2(prob_throw) per (n, tile): n<=1024, 34 tiles
static __device__ float g_l[1024 * 34];

__device__ __forceinline__ void cp16(float* s, const float* g) {
    unsigned sa = (unsigned)__cvta_generic_to_shared(s);
    asm volatile("cp.async.cg.shared.global [%0], [%1], 16;\n" :: "r"(sa), "l"(g));
}

// 2^x for x in ~[-4, 1], FMA-pipe only (no MUFU). Degree-6 Taylor on f in [-0.5,0.5],
// rel err ~1e-7 — far under the 1e-3 tolerance even after a 34-term product.
__device__ __forceinline__ float exp2_fast(float x) {
    float r = rintf(x);
    float f = x - r;
    float p = 1.5403530e-4f;
    p = fmaf(p, f, 1.3333558e-3f);
    p = fmaf(p, f, 9.6181291e-3f);
    p = fmaf(p, f, 5.5504109e-2f);
    p = fmaf(p, f, 2.4022651e-1f);
    p = fmaf(p, f, 6.9314718e-1f);
    p = fmaf(p, f, 1.0f);
    return __int_as_float(__float_as_int(p) + ((int)r << 23));
}

// 1/d for positive normal d, FMA-pipe only. Bit-trick seed (rel err ~0.034)
// + 3 Newton iterations -> ~1 ulp.
__device__ __forceinline__ float rcp_fast(float d) {
    float x = __int_as_float(0x7EF311C3 - __float_as_int(d));
    x = x * fmaf(-d, x, 2.0f);
    x = x * fmaf(-d, x, 2.0f);
    x = x * fmaf(-d, x, 2.0f);
    return x;
}

__global__ void k_prob(const float* __restrict__ meta,
                       const float* __restrict__ wall,
                       const float* __restrict__ W,
                       const float* __restrict__ b,
                       int n) {
    int i = blockIdx.x * blockDim.x + threadIdx.x;
    if (i >= n * 34) return;
    int nn = i / 34;
    int t  = i - nn * 34;
    float p = b[0];
    #pragma unroll
    for (int c = 0; c < 6; c++) p = fmaf(meta[nn * 6 + c], W[c], p);
    const float* wl = wall + ((size_t)nn * 34 + t) * 5;
    #pragma unroll
    for (int j = 0; j < 5; j++) p = fmaf(wl[j], W[6 + j], p);
    g_l[i] = log2f(p);
}

// One block per (n, action a in 0..4): 64 m's, staged in 4 chunks of 16 m's.
// 256 threads = 16 half-warp groups; group g handles m-local g of each chunk.
// Within a group, lane l handles tiles {l, l+16, l+32(l<2)}.
__global__ __launch_bounds__(256, 4)
void k_main(const float* __restrict__ tp,
            const float* __restrict__ fp,
            const float* __restrict__ rp,
            const float* __restrict__ fanc,
            const float* __restrict__ fanm,
            const float* __restrict__ tilec,
            float* __restrict__ outm,
            float* __restrict__ outw) {
    __shared__ __align__(16) float s_tp[2][3808];   // 16 m * 34 tiles * 7 ch
    __shared__ __align__(16) float s_fan[2][1280];  // 16 m * 80
    __shared__ __align__(16) float s_red[2][544];   // 16 m * 34
    __shared__ float s_fc[80];
    __shared__ float s_l[34];
    __shared__ float s_s[34 * 17];
    __shared__ float s_f[16];
    __shared__ float s_mx[34];

    const int tid  = threadIdx.x;
    const int bid  = blockIdx.x;
    const int nIdx = bid / 5;
    const int a    = bid - nIdx * 5;
    const int grp  = tid >> 4;
    const int l16  = tid & 15;

    const size_t mstart = (size_t)nIdx * 320 + a * 64;

    // prologue: issue chunk 0
    {
        const float* g0 = tp + mstart * 238;
        const float* g1 = fp + mstart * 80;
        const float* g2 = rp + mstart * 34;
        for (int i = tid; i < 952; i += 256) cp16(&s_tp[0][i * 4], g0 + i * 4);
        for (int i = tid; i < 320; i += 256) cp16(&s_fan[0][i * 4], g1 + i * 4);
        for (int i = tid; i < 136; i += 256) cp16(&s_red[0][i * 4], g2 + i * 4);
        asm volatile("cp.async.commit_group;\n" ::);
    }
    if (tid < 80) s_fc[tid] = fanc[tid] * fanm[tid];
    if (tid < 34) s_l[tid]  = g_l[nIdx * 34 + tid];
    __syncthreads();

    const float lA = s_l[l16];
    const float lB = s_l[l16 + 16];
    const float lC = (l16 < 2) ? s_l[l16 + 32] : 0.f;

    float acc0 = 0.f, acc1 = 0.f, acc2 = 0.f, facc = 0.f;

    for (int k = 0; k < 4; k++) {
        if (k < 3) {
            const int nb = (k + 1) & 1;
            const size_t mo = mstart + (size_t)(k + 1) * 16;
            const float* g0 = tp + mo * 238;
            const float* g1 = fp + mo * 80;
            const float* g2 = rp + mo * 34;
            for (int i = tid; i < 952; i += 256) cp16(&s_tp[nb][i * 4], g0 + i * 4);
            for (int i = tid; i < 320; i += 256) cp16(&s_fan[nb][i * 4], g1 + i * 4);
            for (int i = tid; i < 136; i += 256) cp16(&s_red[nb][i * 4], g2 + i * 4);
            asm volatile("cp.async.commit_group;\n" ::);
            asm volatile("cp.async.wait_group 1;\n" ::);
        } else {
            asm volatile("cp.async.wait_group 0;\n" ::);
        }
        __syncthreads();

        const int cb = k & 1;
        const float* tpb = &s_tp[cb][grp * 238];
        const float* fnb = &s_fan[cb][grp * 80];
        const float* rdb = &s_red[cb][grp * 34];

        // fan preference sum (80 = 5*16)
        float fs = 0.f;
        #pragma unroll
        for (int j = 0; j < 5; j++) {
            int jj = l16 + (j << 4);
            fs = fmaf(fnb[jj], s_fc[jj], fs);
        }

        // per-tile numerator/denominator partial products
        // terms_summed = t0*p^tnc + t6 + (t3*t2/t4)*t5
        //             == ((t0*e + t6)*t4 + t3*t2*t5) / t4   (hoist the divide)
        float pn, ph;
        {
            const float* c = tpb + l16 * 7;
            float e = exp2_fast(c[1] * lA);
            pn = fmaf(fmaf(c[0], e, c[6]), c[4], c[3] * c[2] * c[5]);
            ph = c[4];
        }
        {
            const float* c = tpb + (l16 + 16) * 7;
            float e = exp2_fast(c[1] * lB);
            pn *= fmaf(fmaf(c[0], e, c[6]), c[4], c[3] * c[2] * c[5]);
            ph *= c[4];
        }
        if (l16 < 2) {
            const float* c = tpb + (l16 + 32) * 7;
            float e = exp2_fast(c[1] * lC);
            pn *= fmaf(fmaf(c[0], e, c[6]), c[4], c[3] * c[2] * c[5]);
            ph *= c[4];
        }

        // butterfly product/sum over the 16-lane group (xor masks stay in-half)
        #pragma unroll
        for (int o = 8; o >= 1; o >>= 1) {
            pn *= __shfl_xor_sync(0xffffffffu, pn, o);
            ph *= __shfl_xor_sync(0xffffffffu, ph, o);
            fs += __shfl_xor_sync(0xffffffffu, fs, o);
        }

        float fpt = pn * rcp_fast(ph) * 100.f * fs;

        acc0 = fmaf(rdb[l16],      fpt, acc0);
        acc1 = fmaf(rdb[l16 + 16], fpt, acc1);
        if (l16 < 2) acc2 = fmaf(rdb[l16 + 32], fpt, acc2);
        facc += fpt;
        __syncthreads();   // buffer cb free for reuse by the next issue
    }

    // cross-group reduction
    s_s[l16 * 17 + grp]        = acc0;
    s_s[(l16 + 16) * 17 + grp] = acc1;
    if (l16 < 2) s_s[(l16 + 32) * 17 + grp] = acc2;
    if (l16 == 0) s_f[grp] = facc;
    __syncthreads();

    if (tid < 34) {
        float tb = 0.f;
        #pragma unroll
        for (int g = 0; g < 16; g++) tb += s_s[tid * 17 + g];
        if (a == 0) outw[nIdx * 34 + tid] = tb * tilec[tid];
        s_mx[tid] = tb;
    }
    __syncthreads();

    if (tid == 0) {
        float v;
        if (a == 0) {
            float fps = 0.f;
            #pragma unroll
            for (int g = 0; g < 16; g++) fps += s_f[g];
            v = fps;                       // final_prob_ops[:,0] overrides slot 0
        } else {
            float mx = s_mx[0];
            #pragma unroll
            for (int t = 1; t < 34; t++) mx = fmaxf(mx, s_mx[t]);
            v = mx;
        }
        outm[nIdx * 5 + a] = v;
    }
}

extern "C" void kernel_launch(void* const* d_in, const int* in_sizes, int n_in,
                              void* d_out, int out_size) {
    const float* meta  = (const float*)d_in[0];
    const float* wall  = (const float*)d_in[1];
    const float* tp    = (const float*)d_in[2];
    const float* fp    = (const float*)d_in[3];
    const float* rp    = (const float*)d_in[4];
    // d_in[5] (count_prep), d_in[6] (chi_peng_count_remain) are unused by the reference
    const float* W     = (const float*)d_in[7];
    const float* b     = (const float*)d_in[8];
    const float* fanc  = (const float*)d_in[9];
    const float* fanm  = (const float*)d_in[10];
    const float* tilec = (const float*)d_in[11];

    int n = in_sizes[0] / 6;   // 1024

    float* outm = (float*)d_out;            // (n,5)
    float* outw = outm + (size_t)n * 5;     // (n,34)

    k_prob<<<(n * 34 + 255) / 256, 256>>>(meta, wall, W, b, n);
    k_main<<<n * 5, 256>>>(tp, fp, rp, fanc, fanm, tilec, outm, outw);
}

// round 2
// speedup vs baseline: 1.0069x; 1.0069x over previous
#include <cuda_runtime.h>

#define STAGES   4
#define CHUNK_M  8
#define TP_F     (CHUNK_M * 238)   // 1904 floats = 7616 B
#define FAN_F    (CHUNK_M * 80)    // 640  floats = 2560 B
#define RED_F    (CHUNK_M * 34)    // 272  floats = 1088 B
#define STAGE_F  (TP_F + FAN_F + RED_F)   // 2816 floats
#define CHUNK_BYTES (STAGE_F * 4)         // 11264 B

// ---- FMA-pipe-only math (no MUFU in the hot loop) ----
__device__ __forceinline__ float exp2_fast(float x) {
    float r = rintf(x);
    float f = x - r;
    float p = 1.5403530e-4f;
    p = fmaf(p, f, 1.3333558e-3f);
    p = fmaf(p, f, 9.6181291e-3f);
    p = fmaf(p, f, 5.5504109e-2f);
    p = fmaf(p, f, 2.4022651e-1f);
    p = fmaf(p, f, 6.9314718e-1f);
    p = fmaf(p, f, 1.0f);
    return __int_as_float(__float_as_int(p) + ((int)r << 23));
}

__device__ __forceinline__ float rcp_fast(float d) {
    float x = __int_as_float(0x7EF311C3 - __float_as_int(d));
    x = x * fmaf(-d, x, 2.0f);
    x = x * fmaf(-d, x, 2.0f);
    x = x * fmaf(-d, x, 2.0f);
    return x;
}

// ---- bulk-async + mbarrier helpers ----
__device__ __forceinline__ void bulk_cp(float* s, const float* g, unsigned bytes, unsigned mbar) {
    unsigned sa = (unsigned)__cvta_generic_to_shared(s);
    asm volatile(
        "cp.async.bulk.shared::cta.global.mbarrier::complete_tx::bytes [%0], [%1], %2, [%3];\n"
        :: "r"(sa), "l"(g), "r"(bytes), "r"(mbar) : "memory");
}

__device__ __forceinline__ void mbar_init(unsigned mbar, unsigned cnt) {
    asm volatile("mbarrier.init.shared.b64 [%0], %1;\n" :: "r"(mbar), "r"(cnt) : "memory");
}

__device__ __forceinline__ void mbar_expect(unsigned mbar, unsigned bytes) {
    asm volatile("mbarrier.arrive.expect_tx.shared.b64 _, [%0], %1;\n"
                 :: "r"(mbar), "r"(bytes) : "memory");
}

__device__ __forceinline__ void mbar_wait(unsigned mbar, unsigned phase) {
    asm volatile(
        "{\n\t"
        ".reg .pred P;\n"
        "LW_%=:\n\t"
        "mbarrier.try_wait.parity.acquire.cta.shared::cta.b64 P, [%0], %1, 0x989680;\n\t"
        "@P bra.uni LD_%=;\n\t"
        "bra.uni LW_%=;\n"
        "LD_%=:\n\t"
        "}"
        :: "r"(mbar), "r"(phase) : "memory");
}

// One block per (n, action a): 64 m's in 8 chunks of 8, 4-stage bulk-async ring.
// 256 threads = 8 warps; warp w handles m-local w of each chunk.
// Lane l handles tile l (and tile l+32 for l<2); butterfly over the full warp.
__global__ __launch_bounds__(256, 4)
void k_main(const float* __restrict__ meta,
            const float* __restrict__ wall,
            const float* __restrict__ tp,
            const float* __restrict__ fp,
            const float* __restrict__ rp,
            const float* __restrict__ W,
            const float* __restrict__ b,
            const float* __restrict__ fanc,
            const float* __restrict__ fanm,
            const float* __restrict__ tilec,
            float* __restrict__ outm,
            float* __restrict__ outw) {
    __shared__ __align__(16) float s_buf[STAGES][STAGE_F];
    __shared__ float s_fc[80];
    __shared__ float s_l[34];
    __shared__ float s_s[34 * 8];
    __shared__ float s_f[8];
    __shared__ float s_mx[34];
    __shared__ __align__(8) unsigned long long s_mbar[STAGES];

    const int tid  = threadIdx.x;
    const int bid  = blockIdx.x;
    const int nIdx = bid / 5;
    const int a    = bid - nIdx * 5;
    const int w    = tid >> 5;
    const int l    = tid & 31;

    const size_t mstart = (size_t)nIdx * 320 + a * 64;
    const unsigned mb0 = (unsigned)__cvta_generic_to_shared(&s_mbar[0]);

    // ---- prologue: barriers + per-block prob_throw (fused former k_prob) ----
    if (tid < STAGES) mbar_init(mb0 + tid * 8, 1);

    if (tid < 34) {
        float p = b[0];
        const float* mt = meta + nIdx * 6;
        #pragma unroll
        for (int c = 0; c < 6; c++) p = fmaf(mt[c], W[c], p);
        const float* wl = wall + ((size_t)nIdx * 34 + tid) * 5;
        #pragma unroll
        for (int j = 0; j < 5; j++) p = fmaf(wl[j], W[6 + j], p);
        s_l[tid] = log2f(p);
    }
    if (tid >= 64 && tid < 144) {
        int j = tid - 64;
        s_fc[j] = fanc[j] * fanm[j];
    }
    __syncthreads();

    // issue chunks 0..3 into stages 0..3
    if (tid == 0) {
        #pragma unroll
        for (int c = 0; c < STAGES; c++) {
            const size_t m0 = mstart + (size_t)c * CHUNK_M;
            unsigned mb = mb0 + c * 8;
            mbar_expect(mb, CHUNK_BYTES);
            bulk_cp(&s_buf[c][0],            tp + m0 * 238, TP_F * 4,  mb);
            bulk_cp(&s_buf[c][TP_F],         fp + m0 * 80,  FAN_F * 4, mb);
            bulk_cp(&s_buf[c][TP_F + FAN_F], rp + m0 * 34,  RED_F * 4, mb);
        }
    }

    const float lA  = s_l[l];
    const float lB  = (l < 2) ? s_l[l + 32] : 0.f;
    const float fcA = s_fc[l];
    const float fcB = s_fc[l + 32];
    const float fcC = (l < 16) ? s_fc[l + 64] : 0.f;

    float accA = 0.f, accB = 0.f, facc = 0.f;

    for (int k = 0; k < 8; k++) {
        const int s  = k & 3;
        const unsigned ph = (k >> 2) & 1;
        mbar_wait(mb0 + s * 8, ph);

        const float* base = &s_buf[s][0];
        const float* tpb = base + w * 238;
        const float* fnb = base + TP_F + w * 80;
        const float* rdb = base + TP_F + FAN_F + w * 34;

        // fan preference partial sum (80 over 32 lanes)
        float fs = fmaf(fnb[l], fcA, fnb[l + 32] * fcB);
        if (l < 16) fs = fmaf(fnb[l + 64], fcC, fs);

        // terms_summed = t0*p^tnc + t6 + (t3*t2/t4)*t5
        //            == ((t0*e + t6)*t4 + t3*t2*t5) / t4   (single divide, hoisted)
        float pn, phd;
        {
            const float* c = tpb + l * 7;
            float e = exp2_fast(c[1] * lA);
            pn  = fmaf(fmaf(c[0], e, c[6]), c[4], c[3] * c[2] * c[5]);
            phd = c[4];
        }
        if (l < 2) {
            const float* c = tpb + (l + 32) * 7;
            float e = exp2_fast(c[1] * lB);
            pn  *= fmaf(fmaf(c[0], e, c[6]), c[4], c[3] * c[2] * c[5]);
            phd *= c[4];
        }

        // full-warp butterfly: product(pn), product(phd), sum(fs)
        #pragma unroll
        for (int o = 16; o >= 1; o >>= 1) {
            pn  *= __shfl_xor_sync(0xffffffffu, pn,  o);
            phd *= __shfl_xor_sync(0xffffffffu, phd, o);
            fs  += __shfl_xor_sync(0xffffffffu, fs,  o);
        }

        const float fpt = pn * rcp_fast(phd) * 100.f * fs;

        accA = fmaf(rdb[l], fpt, accA);
        if (l < 2) accB = fmaf(rdb[l + 32], fpt, accB);
        facc += fpt;

        __syncthreads();  // buffer s fully consumed by all warps

        if (k < 4 && tid == 0) {
            const size_t m0 = mstart + (size_t)(k + 4) * CHUNK_M;
            unsigned mb = mb0 + s * 8;
            mbar_expect(mb, CHUNK_BYTES);
            bulk_cp(&s_buf[s][0],            tp + m0 * 238, TP_F * 4,  mb);
            bulk_cp(&s_buf[s][TP_F],         fp + m0 * 80,  FAN_F * 4, mb);
            bulk_cp(&s_buf[s][TP_F + FAN_F], rp + m0 * 34,  RED_F * 4, mb);
        }
    }

    // ---- cross-warp reduction ----
    s_s[l * 8 + w] = accA;
    if (l < 2) s_s[(l + 32) * 8 + w] = accB;
    if (l == 0) s_f[w] = facc;
    __syncthreads();

    if (tid < 34) {
        float tb = 0.f;
        #pragma unroll
        for (int g = 0; g < 8; g++) tb += s_s[tid * 8 + g];
        if (a == 0) outw[nIdx * 34 + tid] = tb * tilec[tid];
        s_mx[tid] = tb;
    }
    __syncthreads();

    if (tid == 0) {
        float v;
        if (a == 0) {
            float fps = 0.f;
            #pragma unroll
            for (int g = 0; g < 8; g++) fps += s_f[g];
            v = fps;   // final_prob_ops[:,0] overrides slot 0
        } else {
            float mx = s_mx[0];
            #pragma unroll
            for (int t = 1; t < 34; t++) mx = fmaxf(mx, s_mx[t]);
            v = mx;
        }
        outm[nIdx * 5 + a] = v;
    }
}

extern "C" void kernel_launch(void* const* d_in, const int* in_sizes, int n_in,
                              void* d_out, int out_size) {
    const float* meta  = (const float*)d_in[0];
    const float* wall  = (const float*)d_in[1];
    const float* tp    = (const float*)d_in[2];
    const float* fp    = (const float*)d_in[3];
    const float* rp    = (const float*)d_in[4];
    // d_in[5] (count_prep), d_in[6] (chi_peng_count_remain) unused by reference
    const float* W     = (const float*)d_in[7];
    const float* b     = (const float*)d_in[8];
    const float* fanc  = (const float*)d_in[9];
    const float* fanm  = (const float*)d_in[10];
    const float* tilec = (const float*)d_in[11];

    int n = in_sizes[0] / 6;   // 1024

    float* outm = (float*)d_out;          // (n,5)
    float* outw = outm + (size_t)n * 5;   // (n,34)

    k_main<<<n * 5, 256>>>(meta, wall, tp, fp, rp, W, b, fanc, fanm, tilec, outm, outw);
}

// round 3
// speedup vs baseline: 1.0340x; 1.0269x over previous
#include <cuda_runtime.h>

__device__ __forceinline__ void cp16(float* s, const float* g) {
    unsigned sa = (unsigned)__cvta_generic_to_shared(s);
    asm volatile("cp.async.cg.shared.global [%0], [%1], 16;\n" :: "r"(sa), "l"(g));
}

// 2^x for x in ~[-4, 1], FMA-pipe only. Degree-6 poly on f in [-0.5,0.5], rel err ~1e-7.
__device__ __forceinline__ float exp2_fast(float x) {
    float r = rintf(x);
    float f = x - r;
    float p = 1.5403530e-4f;
    p = fmaf(p, f, 1.3333558e-3f);
    p = fmaf(p, f, 9.6181291e-3f);
    p = fmaf(p, f, 5.5504109e-2f);
    p = fmaf(p, f, 2.4022651e-1f);
    p = fmaf(p, f, 6.9314718e-1f);
    p = fmaf(p, f, 1.0f);
    return __int_as_float(__float_as_int(p) + ((int)r << 23));
}

// 1/d for positive normal d, FMA-pipe only (bit-trick seed + 3 Newton steps).
__device__ __forceinline__ float rcp_fast(float d) {
    float x = __int_as_float(0x7EF311C3 - __float_as_int(d));
    x = x * fmaf(-d, x, 2.0f);
    x = x * fmaf(-d, x, 2.0f);
    x = x * fmaf(-d, x, 2.0f);
    return x;
}

// One block per (n, action a in 0..4): 64 m's, staged in 4 chunks of 16 m's,
// 2-deep cp.async.cg pipeline (Round-1 proven load path).
// 256 threads = 16 half-warp groups; group g handles m-local g of each chunk.
// Within a group, lane l handles tiles {l, l+16, l+32(l<2)}.
// prob_throw (former k_prob) is computed in the prologue, fused.
__global__ __launch_bounds__(256, 4)
void k_main(const float* __restrict__ meta,
            const float* __restrict__ wall,
            const float* __restrict__ tp,
            const float* __restrict__ fp,
            const float* __restrict__ rp,
            const float* __restrict__ W,
            const float* __restrict__ b,
            const float* __restrict__ fanc,
            const float* __restrict__ fanm,
            const float* __restrict__ tilec,
            float* __restrict__ outm,
            float* __restrict__ outw) {
    __shared__ __align__(16) float s_tp[2][3808];   // 16 m * 34 tiles * 7 ch
    __shared__ __align__(16) float s_fan[2][1280];  // 16 m * 80
    __shared__ __align__(16) float s_red[2][544];   // 16 m * 34
    __shared__ float s_fc[80];
    __shared__ float s_l[34];
    __shared__ float s_s[34 * 17];
    __shared__ float s_f[16];
    __shared__ float s_mx[34];

    const int tid  = threadIdx.x;
    const int bid  = blockIdx.x;
    const int nIdx = bid / 5;
    const int a    = bid - nIdx * 5;
    const int grp  = tid >> 4;
    const int l16  = tid & 15;

    const size_t mstart = (size_t)nIdx * 320 + a * 64;

    // prologue: issue chunk 0 first so loads fly while we compute prob_throw
    {
        const float* g0 = tp + mstart * 238;
        const float* g1 = fp + mstart * 80;
        const float* g2 = rp + mstart * 34;
        for (int i = tid; i < 952; i += 256) cp16(&s_tp[0][i * 4], g0 + i * 4);
        for (int i = tid; i < 320; i += 256) cp16(&s_fan[0][i * 4], g1 + i * 4);
        for (int i = tid; i < 136; i += 256) cp16(&s_red[0][i * 4], g2 + i * 4);
        asm volatile("cp.async.commit_group;\n" ::);
    }

    // fused prob_throw: per-tile Linear(11,1) then log2 (tiny; hidden under loads)
    if (tid < 34) {
        float p = b[0];
        const float* mt = meta + nIdx * 6;
        #pragma unroll
        for (int c = 0; c < 6; c++) p = fmaf(mt[c], W[c], p);
        const float* wl = wall + ((size_t)nIdx * 34 + tid) * 5;
        #pragma unroll
        for (int j = 0; j < 5; j++) p = fmaf(wl[j], W[6 + j], p);
        s_l[tid] = log2f(p);
    }
    if (tid >= 64 && tid < 144) {
        int j = tid - 64;
        s_fc[j] = fanc[j] * fanm[j];
    }
    __syncthreads();

    const float lA = s_l[l16];
    const float lB = s_l[l16 + 16];
    const float lC = (l16 < 2) ? s_l[l16 + 32] : 0.f;

    float acc0 = 0.f, acc1 = 0.f, acc2 = 0.f, facc = 0.f;

    for (int k = 0; k < 4; k++) {
        if (k < 3) {
            const int nb = (k + 1) & 1;
            const size_t mo = mstart + (size_t)(k + 1) * 16;
            const float* g0 = tp + mo * 238;
            const float* g1 = fp + mo * 80;
            const float* g2 = rp + mo * 34;
            for (int i = tid; i < 952; i += 256) cp16(&s_tp[nb][i * 4], g0 + i * 4);
            for (int i = tid; i < 320; i += 256) cp16(&s_fan[nb][i * 4], g1 + i * 4);
            for (int i = tid; i < 136; i += 256) cp16(&s_red[nb][i * 4], g2 + i * 4);
            asm volatile("cp.async.commit_group;\n" ::);
            asm volatile("cp.async.wait_group 1;\n" ::);
        } else {
            asm volatile("cp.async.wait_group 0;\n" ::);
        }
        __syncthreads();

        const int cb = k & 1;
        const float* tpb = &s_tp[cb][grp * 238];
        const float* fnb = &s_fan[cb][grp * 80];
        const float* rdb = &s_red[cb][grp * 34];

        // fan preference sum (80 = 5*16)
        float fs = 0.f;
        #pragma unroll
        for (int j = 0; j < 5; j++) {
            int jj = l16 + (j << 4);
            fs = fmaf(fnb[jj], s_fc[jj], fs);
        }

        // terms_summed = t0*p^tnc + t6 + (t3*t2/t4)*t5
        //             == ((t0*e + t6)*t4 + t3*t2*t5) / t4   (hoist the divide)
        float pn, ph;
        {
            const float* c = tpb + l16 * 7;
            float e = exp2_fast(c[1] * lA);
            pn = fmaf(fmaf(c[0], e, c[6]), c[4], c[3] * c[2] * c[5]);
            ph = c[4];
        }
        {
            const float* c = tpb + (l16 + 16) * 7;
            float e = exp2_fast(c[1] * lB);
            pn *= fmaf(fmaf(c[0], e, c[6]), c[4], c[3] * c[2] * c[5]);
            ph *= c[4];
        }
        if (l16 < 2) {
            const float* c = tpb + (l16 + 32) * 7;
            float e = exp2_fast(c[1] * lC);
            pn *= fmaf(fmaf(c[0], e, c[6]), c[4], c[3] * c[2] * c[5]);
            ph *= c[4];
        }

        // butterfly product/sum over the 16-lane group (xor masks stay in-half)
        #pragma unroll
        for (int o = 8; o >= 1; o >>= 1) {
            pn *= __shfl_xor_sync(0xffffffffu, pn, o);
            ph *= __shfl_xor_sync(0xffffffffu, ph, o);
            fs += __shfl_xor_sync(0xffffffffu, fs, o);
        }

        float fpt = pn * rcp_fast(ph) * 100.f * fs;

        acc0 = fmaf(rdb[l16],      fpt, acc0);
        acc1 = fmaf(rdb[l16 + 16], fpt, acc1);
        if (l16 < 2) acc2 = fmaf(rdb[l16 + 32], fpt, acc2);
        facc += fpt;
        __syncthreads();   // buffer cb free for reuse by the next issue
    }

    // cross-group reduction
    s_s[l16 * 17 + grp]        = acc0;
    s_s[(l16 + 16) * 17 + grp] = acc1;
    if (l16 < 2) s_s[(l16 + 32) * 17 + grp] = acc2;
    if (l16 == 0) s_f[grp] = facc;
    __syncthreads();

    if (tid < 34) {
        float tb = 0.f;
        #pragma unroll
        for (int g = 0; g < 16; g++) tb += s_s[tid * 17 + g];
        if (a == 0) outw[nIdx * 34 + tid] = tb * tilec[tid];
        s_mx[tid] = tb;
    }
    __syncthreads();

    if (tid == 0) {
        float v;
        if (a == 0) {
            float fps = 0.f;
            #pragma unroll
            for (int g = 0; g < 16; g++) fps += s_f[g];
            v = fps;                       // final_prob_ops[:,0] overrides slot 0
        } else {
            float mx = s_mx[0];
            #pragma unroll
            for (int t = 1; t < 34; t++) mx = fmaxf(mx, s_mx[t]);
            v = mx;
        }
        outm[nIdx * 5 + a] = v;
    }
}

extern "C" void kernel_launch(void* const* d_in, const int* in_sizes, int n_in,
                              void* d_out, int out_size) {
    const float* meta  = (const float*)d_in[0];
    const float* wall  = (const float*)d_in[1];
    const float* tp    = (const float*)d_in[2];
    const float* fp    = (const float*)d_in[3];
    const float* rp    = (const float*)d_in[4];
    // d_in[5] (count_prep), d_in[6] (chi_peng_count_remain) unused by the reference
    const float* W     = (const float*)d_in[7];
    const float* b     = (const float*)d_in[8];
    const float* fanc  = (const float*)d_in[9];
    const float* fanm  = (const float*)d_in[10];
    const float* tilec = (const float*)d_in[11];

    int n = in_sizes[0] / 6;   // 1024

    float* outm = (float*)d_out;          // (n,5)
    float* outw = outm + (size_t)n * 5;   // (n,34)

    k_main<<<n * 5, 256>>>(meta, wall, tp, fp, rp, W, b, fanc, fanm, tilec, outm, outw);
}